// round 3
// baseline (speedup 1.0000x reference)
#include <cuda_runtime.h>
#include <cuda_fp16.h>
#include <cstdint>

#define SEQ   4096
#define BATCH 32
#define HID   512
#define NROWS (SEQ*BATCH)   // 131072

// ---------------- device scratch ----------------
__device__ __half g_Wh[HID*HID];               // fp16 weights [o][h]
__device__ float g_sim[NROWS];                 // similarity, index = s*32+b
__device__ float g_probs[BATCH*SEQ];           // softmax probs [b][s]
__device__ float g_part[BATCH*32*HID];         // pooling partials [b][chunk][h]

// ---------------- helpers ----------------
__device__ __forceinline__ uint32_t smem_u32(const void* p){
    uint32_t a;
    asm("{ .reg .u64 t; cvta.to.shared.u64 t, %1; cvt.u32.u64 %0, t; }" : "=r"(a) : "l"(p));
    return a;
}
__device__ __forceinline__ float tanh_fast(float x){
    float y; asm("tanh.approx.f32 %0, %1;" : "=f"(y) : "f"(x)); return y;
}
__device__ __forceinline__ void ldsm_x4(uint32_t* r, uint32_t addr){
    asm volatile("ldmatrix.sync.aligned.m8n8.x4.shared.b16 {%0,%1,%2,%3}, [%4];"
        : "=r"(r[0]),"=r"(r[1]),"=r"(r[2]),"=r"(r[3]) : "r"(addr));
}
__device__ __forceinline__ void mma_fp16(float* d, const uint32_t* a, const uint32_t* b){
    asm volatile("mma.sync.aligned.m16n8k16.row.col.f32.f16.f16.f32 "
        "{%0,%1,%2,%3}, {%4,%5,%6,%7}, {%8,%9}, {%0,%1,%2,%3};"
        : "+f"(d[0]),"+f"(d[1]),"+f"(d[2]),"+f"(d[3])
        : "r"(a[0]),"r"(a[1]),"r"(a[2]),"r"(a[3]), "r"(b[0]),"r"(b[1]));
}

// ---------------- smem layout (bytes) ----------------
// A: 128 rows x 520 fp16 (stride pad 8)  -> 133120
// B: two bufs 128 x 72 fp16              -> 18432 each
#define SM_A     0
#define SM_B0    133120
#define SM_B1    151552
#define SM_BIAS  169984
#define SM_CTX   172032
#define SM_RED   174080
#define SM_TOTAL 176128

// ---------------- kernel 1: W -> fp16 ----------------
__global__ void wconv_kernel(const float* __restrict__ W){
    for (int i = blockIdx.x*blockDim.x + threadIdx.x; i < HID*HID; i += gridDim.x*blockDim.x)
        g_Wh[i] = __float2half_rn(W[i]);
}

// ---------------- kernel 2: sim[row] = ctx . tanh(W x_row + bias) ----------------
// CTA: 128 rows x 512 cols, K=512. A (x, fp16) smem-resident, loaded per-k-chunk
// during nt=0. W streamed as 128x64 tiles, double buffered, register-prefetched.
__global__ void __launch_bounds__(512,1) sim_kernel(const float* __restrict__ x,
                                                    const float* __restrict__ bias,
                                                    const float* __restrict__ ctx){
    extern __shared__ char smem[];
    const uint32_t sb = smem_u32(smem);
    const int tid = threadIdx.x, wid = tid>>5, lane = tid&31;
    const int wm = (wid&3)*32, wn = (wid>>2)*32;
    const long row0 = (long)blockIdx.x * 128;

    float* bias_s = (float*)(smem + SM_BIAS);
    float* ctx_s  = (float*)(smem + SM_CTX);
    if (tid < 512){ bias_s[tid] = bias[tid]; ctx_s[tid] = ctx[tid]; }

    // ldmatrix per-lane address offsets
    const uint32_t a_lane_off = (uint32_t)(((lane&7) + ((lane>>3)&1)*8)*1040 + ((lane>>4)<<4));
    const uint32_t b_lane_off = (uint32_t)(((lane&7) + ((lane>>4)<<3))*144 + (((lane>>3)&1)<<4));

    const float4* xv = (const float4*)(x + (size_t)row0 * HID);

    float4 aReg[4];
    uint4  bReg[2];

    // prologue: A chunk 0, B tile (nt=0,kc=0)
    #pragma unroll
    for (int i=0;i<4;i++){ int idx=tid+i*512; int r=idx>>4, c4=idx&15;
        aReg[i] = xv[(size_t)r*128 + c4]; }
    #pragma unroll
    for (int i=0;i<2;i++){ int idx=tid+i*512; int n=idx>>3, cb=idx&7;
        bReg[i] = *(const uint4*)(g_Wh + (size_t)n*512 + cb*8); }
    #pragma unroll
    for (int i=0;i<4;i++){ int idx=tid+i*512; int r=idx>>4, c4=idx&15;
        __half2 p0 = __floats2half2_rn(aReg[i].x, aReg[i].y);
        __half2 p1 = __floats2half2_rn(aReg[i].z, aReg[i].w);
        uint2 u; u.x = *reinterpret_cast<uint32_t*>(&p0); u.y = *reinterpret_cast<uint32_t*>(&p1);
        *reinterpret_cast<uint2*>(smem + SM_A + r*1040 + c4*8) = u; }
    #pragma unroll
    for (int i=0;i<2;i++){ int idx=tid+i*512; int n=idx>>3, cb=idx&7;
        *reinterpret_cast<uint4*>(smem + SM_B0 + n*144 + cb*16) = bReg[i]; }
    __syncthreads();

    float acc[2][4][4];
    #pragma unroll
    for (int a=0;a<2;a++)
        #pragma unroll
        for (int b=0;b<4;b++)
            #pragma unroll
            for (int c=0;c<4;c++) acc[a][b][c] = 0.f;
    float rowsum[4] = {0.f,0.f,0.f,0.f};

    for (int it = 0; it < 32; ++it){
        const int nt = it>>3, kc = it&7, buf = it&1;
        const int itn = it + 1;
        const bool more = itn < 32;

        // prefetch next tiles into registers
        if (more){
            const int nn = itn>>3, nk = itn&7;
            #pragma unroll
            for (int i=0;i<2;i++){ int idx=tid+i*512; int n=idx>>3, cb=idx&7;
                bReg[i] = *(const uint4*)(g_Wh + (size_t)(nn*128+n)*512 + nk*64 + cb*8); }
            if (itn < 8){
                #pragma unroll
                for (int i=0;i<4;i++){ int idx=tid+i*512; int r=idx>>4, c4=idx&15;
                    aReg[i] = xv[(size_t)r*128 + itn*16 + c4]; }
            }
        }

        // mma over this (nt,kc) tile
        const uint32_t Ab = sb + SM_A + (uint32_t)(wm*1040) + a_lane_off + (uint32_t)(kc*128);
        const uint32_t Bb = sb + (buf ? SM_B1 : SM_B0) + (uint32_t)(wn*144) + b_lane_off;
        #pragma unroll
        for (int ks=0; ks<4; ++ks){
            uint32_t af[2][4], bf2[2][4];
            ldsm_x4(af[0],  Ab + ks*32);
            ldsm_x4(af[1],  Ab + 16*1040 + ks*32);
            ldsm_x4(bf2[0], Bb + ks*32);
            ldsm_x4(bf2[1], Bb + 16*144 + ks*32);
            #pragma unroll
            for (int mf=0; mf<2; ++mf)
                #pragma unroll
                for (int nf=0; nf<4; ++nf)
                    mma_fp16(acc[mf][nf], af[mf], &bf2[nf>>1][(nf&1)*2]);
        }

        // after last k-chunk of this nt: fold into per-row sums, reset accums
        if (kc == 7){
            #pragma unroll
            for (int mf=0; mf<2; ++mf)
                #pragma unroll
                for (int nf=0; nf<4; ++nf){
                    const int c = nt*128 + wn + nf*8 + (lane&3)*2;
                    float* a = acc[mf][nf];
                    rowsum[mf*2+0] += tanh_fast(a[0]+bias_s[c])*ctx_s[c]
                                    + tanh_fast(a[1]+bias_s[c+1])*ctx_s[c+1];
                    rowsum[mf*2+1] += tanh_fast(a[2]+bias_s[c])*ctx_s[c]
                                    + tanh_fast(a[3]+bias_s[c+1])*ctx_s[c+1];
                    a[0]=a[1]=a[2]=a[3]=0.f;
                }
        }

        // store prefetched tiles into the other buffer
        if (more){
            #pragma unroll
            for (int i=0;i<2;i++){ int idx=tid+i*512; int n=idx>>3, cb=idx&7;
                *reinterpret_cast<uint4*>(smem + ((itn&1) ? SM_B1 : SM_B0) + n*144 + cb*16) = bReg[i]; }
            if (itn < 8){
                #pragma unroll
                for (int i=0;i<4;i++){ int idx=tid+i*512; int r=idx>>4, c4=idx&15;
                    __half2 p0 = __floats2half2_rn(aReg[i].x, aReg[i].y);
                    __half2 p1 = __floats2half2_rn(aReg[i].z, aReg[i].w);
                    uint2 u; u.x = *reinterpret_cast<uint32_t*>(&p0); u.y = *reinterpret_cast<uint32_t*>(&p1);
                    *reinterpret_cast<uint2*>(smem + SM_A + r*1040 + (itn*16+c4)*8) = u; }
            }
        }
        __syncthreads();
    }

    // reduce rowsum across the 4 lanes sharing each row
    #pragma unroll
    for (int j=0;j<4;j++){
        rowsum[j] += __shfl_xor_sync(0xffffffffu, rowsum[j], 1);
        rowsum[j] += __shfl_xor_sync(0xffffffffu, rowsum[j], 2);
    }
    float* red = (float*)(smem + SM_RED);
    if ((lane&3) == 0){
        const int r4 = lane>>2;
        red[(wid>>2)*128 + wm + r4     ] = rowsum[0];
        red[(wid>>2)*128 + wm + r4 + 8 ] = rowsum[1];
        red[(wid>>2)*128 + wm + r4 + 16] = rowsum[2];
        red[(wid>>2)*128 + wm + r4 + 24] = rowsum[3];
    }
    __syncthreads();
    if (tid < 128)
        g_sim[row0 + tid] = red[tid] + red[128+tid] + red[256+tid] + red[384+tid];
}

// ---------------- kernel 3: softmax over seq, per batch ----------------
__global__ void __launch_bounds__(256) softmax_kernel(){
    const int b = blockIdx.x, tid = threadIdx.x;
    float vals[16];
    float mx = -3.4e38f;
    #pragma unroll
    for (int i = 0; i < 16; ++i){
        int s = i * 256 + tid;
        float v = g_sim[s * 32 + b];
        vals[i] = v;
        mx = fmaxf(mx, v);
    }
    for (int o = 16; o; o >>= 1) mx = fmaxf(mx, __shfl_xor_sync(0xffffffffu, mx, o));
    __shared__ float red[8], red2[8];
    if ((tid & 31) == 0) red[tid >> 5] = mx;
    __syncthreads();
    mx = red[0];
    #pragma unroll
    for (int i = 1; i < 8; ++i) mx = fmaxf(mx, red[i]);

    float sum = 0.f;
    #pragma unroll
    for (int i = 0; i < 16; ++i){ float e = __expf(vals[i] - mx); vals[i] = e; sum += e; }
    for (int o = 16; o; o >>= 1) sum += __shfl_xor_sync(0xffffffffu, sum, o);
    if ((tid & 31) == 0) red2[tid >> 5] = sum;
    __syncthreads();
    sum = 0.f;
    #pragma unroll
    for (int i = 0; i < 8; ++i) sum += red2[i];
    const float inv = 1.0f / sum;
    #pragma unroll
    for (int i = 0; i < 16; ++i) g_probs[b * SEQ + i * 256 + tid] = vals[i] * inv;
}

// ---------------- kernel 4: pooling partials over seq chunks ----------------
__global__ void __launch_bounds__(128) attend_kernel(const float* __restrict__ x){
    const int b = blockIdx.y, ck = blockIdx.x, tid = threadIdx.x;
    __shared__ float ps[128];
    const int s0 = ck * 128;
    ps[tid] = g_probs[b * SEQ + s0 + tid];
    __syncthreads();
    float4 acc = make_float4(0.f, 0.f, 0.f, 0.f);
    #pragma unroll 4
    for (int i = 0; i < 128; ++i){
        const int srow = (s0 + i) * 32 + b;
        const float4* xp = (const float4*)(x + (size_t)srow * HID);
        float4 v = xp[tid];
        const float p = ps[i];
        acc.x += v.x * p; acc.y += v.y * p; acc.z += v.z * p; acc.w += v.w * p;
    }
    float4* dst = (float4*)(g_part + (size_t)(b * 32 + ck) * HID);
    dst[tid] = acc;
}

// ---------------- kernel 5: deterministic partial reduction ----------------
__global__ void __launch_bounds__(512) reduce_kernel(float* __restrict__ out){
    const int b = blockIdx.x, h = threadIdx.x;
    float s = 0.f;
    #pragma unroll
    for (int c = 0; c < 32; ++c) s += g_part[(size_t)(b * 32 + c) * HID + h];
    out[b * HID + h] = s;
}

// ---------------- launch ----------------
extern "C" void kernel_launch(void* const* d_in, const int* in_sizes, int n_in,
                              void* d_out, int out_size){
    const float* x    = (const float*)d_in[0];
    const float* W    = (const float*)d_in[1];
    const float* bias = (const float*)d_in[2];
    const float* ctx  = (const float*)d_in[3];
    float* out = (float*)d_out;

    cudaFuncSetAttribute(sim_kernel, cudaFuncAttributeMaxDynamicSharedMemorySize, SM_TOTAL);

    wconv_kernel<<<256, 256>>>(W);
    sim_kernel<<<NROWS / 128, 512, SM_TOTAL>>>(x, bias, ctx);
    softmax_kernel<<<BATCH, 256>>>();
    attend_kernel<<<dim3(32, BATCH), 128>>>(x);
    reduce_kernel<<<BATCH, 512>>>(out);
}